// round 12
// baseline (speedup 1.0000x reference)
#include <cuda_runtime.h>

#define K 8
#define BLK 1024                // 32 warps: 2 rows x 16 offset chunks
#define NBLK 128                // single wave, one block per SM
#define L2E 1.4426950408889634f
#define C1  (L2E / 9.0f)

__device__ float g_part[16 * NBLK];   // transposed [component][block]
__device__ unsigned int g_count = 0;

#define FULL 0xFFFFFFFFu

// One neighbor row (DX,DY): 3 coalesced loads, then DZ pairs via shuffles only.
#define ROWS(DX, DY, DZLO, DZHI) { \
    const int xx = x + (DX); \
    const int yy = y + (DY); \
    if (xx < 8 && (unsigned)yy < 32u) {   /* warp-uniform branch */ \
        const int jr = (xx << 10) + (yy << 5) + lane; \
        const float fj = __ldg(patch + jr); \
        const float4 qa = __ldg(prob4 + 2 * jr); \
        const float4 qb = __ldg(prob4 + 2 * jr + 1); \
        _Pragma("unroll") \
        for (int dz = (DZLO); dz <= (DZHI); dz++) { \
            const int src = lane + dz; \
            const int sm5 = src & 31; \
            const float fjn = __shfl_sync(FULL, fj, sm5); \
            const float df = fi - fjn; \
            const float e2 = fmaf(df * df, -C1, \
                -(float)((DX)*(DX) + (DY)*(DY) + dz*dz) * L2E); \
            float w; asm("ex2.approx.f32 %0, %1;" : "=f"(w) : "f"(e2)); \
            w = ((unsigned)src < 32u) ? w : 0.0f; \
            s0 = fmaf(w, __shfl_sync(FULL, qa.x, sm5), s0); \
            s1 = fmaf(w, __shfl_sync(FULL, qa.y, sm5), s1); \
            s2 = fmaf(w, __shfl_sync(FULL, qa.z, sm5), s2); \
            s3 = fmaf(w, __shfl_sync(FULL, qa.w, sm5), s3); \
            s4 = fmaf(w, __shfl_sync(FULL, qb.x, sm5), s4); \
            s5 = fmaf(w, __shfl_sync(FULL, qb.y, sm5), s5); \
            s6 = fmaf(w, __shfl_sync(FULL, qb.z, sm5), s6); \
            s7 = fmaf(w, __shfl_sync(FULL, qb.w, sm5), s7); \
            sw += w; \
        } \
    } }

__global__ __launch_bounds__(BLK, 1) void soft_ncuts_fused(
    const float* __restrict__ patch,
    const float* __restrict__ prob,
    float* __restrict__ out)
{
    const int tid   = threadIdx.x;
    const int lane  = tid & 31;          // = z
    const int warp  = tid >> 5;          // 0..31
    const int chunk = warp >> 1;         // 0..15 (offset chunk)
    const int rowl  = warp & 1;          // which of the block's 2 rows
    const int gid   = (int)blockIdx.x * 2 + rowl;   // 0..255 (x,y) row id
    const int x = gid >> 5;              // 0..7
    const int y = gid & 31;              // 0..31
    const int i = (x << 10) + (y << 5) + lane;

    const float4* __restrict__ prob4 = reinterpret_cast<const float4*>(prob);
    const float fi = __ldg(patch + i);
    const float4 pa = __ldg(prob4 + 2 * i);
    const float4 pb = __ldg(prob4 + 2 * i + 1);

    float s0 = 0.f, s1 = 0.f, s2 = 0.f, s3 = 0.f;
    float s4 = 0.f, s5 = 0.f, s6 = 0.f, s7 = 0.f, sw = 0.f;

    // 46 strictly-positive offsets (d^2 <= 8) in 16 chunks of <=3 pairs
    switch (chunk) {
        case  0: ROWS(0,0,1,2)   ROWS(2,-2,0,0)   break; // 3 [diag]
        case  1: ROWS(0,1,-2,0)                   break; // 3
        case  2: ROWS(0,1,1,2)   ROWS(2,2,0,0)    break; // 3
        case  3: ROWS(0,2,-2,0)                   break; // 3
        case  4: ROWS(0,2,1,2)   ROWS(1,-2,-1,-1) break; // 3
        case  5: ROWS(1,-2,0,1)  ROWS(2,-1,-1,-1) break; // 3
        case  6: ROWS(1,-1,-2,0)                  break; // 3
        case  7: ROWS(1,-1,1,2)  ROWS(2,-1,0,0)   break; // 3
        case  8: ROWS(1,0,-2,0)                   break; // 3
        case  9: ROWS(1,0,1,2)   ROWS(2,-1,1,1)   break; // 3
        case 10: ROWS(1,1,-2,0)                   break; // 3
        case 11: ROWS(1,1,1,2)   ROWS(2,1,-1,-1)  break; // 3
        case 12: ROWS(1,2,-1,1)                   break; // 3
        case 13: ROWS(2,0,-2,0)                   break; // 3
        case 14: ROWS(2,0,1,2)   ROWS(2,1,0,0)    break; // 3
        case 15: ROWS(2,1,1,1)                    break; // 1
    }

    // per-thread combine (symmetry: num += P*(2s + diag*P), den += P*(sw+diag) + s)
    const float diag = (chunk == 0) ? 1.0f : 0.0f;

    float v[16];
    v[0] = pa.x * fmaf(diag, pa.x, 2.f * s0);
    v[1] = pa.y * fmaf(diag, pa.y, 2.f * s1);
    v[2] = pa.z * fmaf(diag, pa.z, 2.f * s2);
    v[3] = pa.w * fmaf(diag, pa.w, 2.f * s3);
    v[4] = pb.x * fmaf(diag, pb.x, 2.f * s4);
    v[5] = pb.y * fmaf(diag, pb.y, 2.f * s5);
    v[6] = pb.z * fmaf(diag, pb.z, 2.f * s6);
    v[7] = pb.w * fmaf(diag, pb.w, 2.f * s7);
    const float swd = sw + diag;
    v[8]  = fmaf(pa.x, swd, s0);
    v[9]  = fmaf(pa.y, swd, s1);
    v[10] = fmaf(pa.z, swd, s2);
    v[11] = fmaf(pa.w, swd, s3);
    v[12] = fmaf(pb.x, swd, s4);
    v[13] = fmaf(pb.y, swd, s5);
    v[14] = fmaf(pb.z, swd, s6);
    v[15] = fmaf(pb.w, swd, s7);

    // packed multi-value warp reduction (31 shuffles)
#pragma unroll
    for (int t = 0; t < 16; t++) v[t] += __shfl_xor_sync(FULL, v[t], 16);
    float u[8];
#pragma unroll
    for (int t = 0; t < 8; t++) {
        u[t] = (lane & 16) ? v[t + 8] : v[t];
        u[t] += __shfl_xor_sync(FULL, u[t], 8);
    }
    float w4[4];
#pragma unroll
    for (int t = 0; t < 4; t++) {
        w4[t] = (lane & 8) ? u[t + 4] : u[t];
        w4[t] += __shfl_xor_sync(FULL, w4[t], 4);
    }
    float y2[2];
#pragma unroll
    for (int t = 0; t < 2; t++) {
        y2[t] = (lane & 4) ? w4[t + 2] : w4[t];
        y2[t] += __shfl_xor_sync(FULL, y2[t], 2);
    }
    float z1 = (lane & 2) ? y2[1] : y2[0];
    z1 += __shfl_xor_sync(FULL, z1, 1);
    // lanes 2t, 2t+1 hold the warp total of v[t]

    __shared__ float sm[32 * 17];        // stride 17: conflict-free column reads
    __shared__ unsigned int s_ticket;
    if (!(lane & 1)) sm[warp * 17 + (lane >> 1)] = z1;
    __syncthreads();

    // parallel cross-warp reduce: warp c (of 16) sums component c over 32 warps;
    // writer lanes fence their own store before the block arrives at the ticket.
    if (tid < 512) {
        const int c  = tid >> 5;
        const int sg = tid & 31;
        float a = sm[sg * 17 + c];
#pragma unroll
        for (int o = 16; o > 0; o >>= 1) a += __shfl_xor_sync(FULL, a, o);
        if (sg == 0) {
            g_part[c * NBLK + (int)blockIdx.x] = a;
            __threadfence();             // writers only
        }
    }

    // ---- fused finalize: last block reduces 16 x 128 partials ----
    __syncthreads();
    if (tid == 0) s_ticket = atomicAdd(&g_count, 1u);
    __syncthreads();
    if (s_ticket != NBLK - 1) return;
    __threadfence();                     // acquire side (last block only)

    if (tid < 256) {
        const int c  = tid >> 4;         // component 0..15 (half-warp each)
        const int sg = tid & 15;
        const float4* __restrict__ g4 =
            reinterpret_cast<const float4*>(g_part) + c * 32 + sg * 2;
        const float4 p = __ldcg(g4);
        const float4 q = __ldcg(g4 + 1);
        float a = ((p.x + p.y) + (p.z + p.w)) + ((q.x + q.y) + (q.z + q.w));
#pragma unroll
        for (int o = 8; o > 0; o >>= 1)
            a += __shfl_xor_sync(FULL, a, o);
        if (sg == 0) sm[c] = a;
    }
    __syncthreads();
    if (tid == 0) {
        float loss = (float)K;
#pragma unroll
        for (int t = 0; t < 8; t++) loss -= sm[t] / sm[8 + t];
        out[0] = loss;
        g_count = 0;                    // reset for graph replay
    }
}

extern "C" void kernel_launch(void* const* d_in, const int* in_sizes, int n_in,
                              void* d_out, int out_size)
{
    const float* patch = (const float*)d_in[0];
    const float* prob  = (const float*)d_in[1];
    float* out = (float*)d_out;

    soft_ncuts_fused<<<NBLK, BLK>>>(patch, prob, out);
}

// round 13
// speedup vs baseline: 1.0489x; 1.0489x over previous
#include <cuda_runtime.h>

#define K 8
#define BLK 1024                // 32 warps: 2 rows x 16 offset chunks
#define NBLK 128                // single wave, one block per SM
#define L2E 1.4426950408889634f
#define C1  (L2E / 9.0f)

__device__ float g_part[16 * NBLK];   // transposed [component][block]
__device__ unsigned int g_count = 0;

#define FULL 0xFFFFFFFFu

// One neighbor row (DX,DY): 3 coalesced loads, then DZ pairs via shuffles only.
#define ROWS(DX, DY, DZLO, DZHI) { \
    const int xx = x + (DX); \
    const int yy = y + (DY); \
    if (xx < 8 && (unsigned)yy < 32u) {   /* warp-uniform branch */ \
        const int jr = (xx << 10) + (yy << 5) + lane; \
        const float fj = __ldg(patch + jr); \
        const float4 qa = __ldg(prob4 + 2 * jr); \
        const float4 qb = __ldg(prob4 + 2 * jr + 1); \
        _Pragma("unroll") \
        for (int dz = (DZLO); dz <= (DZHI); dz++) { \
            const int src = lane + dz; \
            const int sm5 = src & 31; \
            const float fjn = __shfl_sync(FULL, fj, sm5); \
            const float df = fi - fjn; \
            const float e2 = fmaf(df * df, -C1, \
                -(float)((DX)*(DX) + (DY)*(DY) + dz*dz) * L2E); \
            float w; asm("ex2.approx.f32 %0, %1;" : "=f"(w) : "f"(e2)); \
            w = ((unsigned)src < 32u) ? w : 0.0f; \
            s0 = fmaf(w, __shfl_sync(FULL, qa.x, sm5), s0); \
            s1 = fmaf(w, __shfl_sync(FULL, qa.y, sm5), s1); \
            s2 = fmaf(w, __shfl_sync(FULL, qa.z, sm5), s2); \
            s3 = fmaf(w, __shfl_sync(FULL, qa.w, sm5), s3); \
            s4 = fmaf(w, __shfl_sync(FULL, qb.x, sm5), s4); \
            s5 = fmaf(w, __shfl_sync(FULL, qb.y, sm5), s5); \
            s6 = fmaf(w, __shfl_sync(FULL, qb.z, sm5), s6); \
            s7 = fmaf(w, __shfl_sync(FULL, qb.w, sm5), s7); \
            sw += w; \
        } \
    } }

__global__ __launch_bounds__(BLK, 1) void soft_ncuts_fused(
    const float* __restrict__ patch,
    const float* __restrict__ prob,
    float* __restrict__ out)
{
    const int tid   = threadIdx.x;
    const int lane  = tid & 31;          // = z
    const int warp  = tid >> 5;          // 0..31
    const int chunk = warp >> 1;         // 0..15 (offset chunk)
    const int rowl  = warp & 1;          // which of the block's 2 rows
    const int gid   = (int)blockIdx.x * 2 + rowl;   // 0..255 (x,y) row id
    const int x = gid >> 5;              // 0..7
    const int y = gid & 31;              // 0..31
    const int i = (x << 10) + (y << 5) + lane;

    const float4* __restrict__ prob4 = reinterpret_cast<const float4*>(prob);
    const float fi = __ldg(patch + i);
    const float4 pa = __ldg(prob4 + 2 * i);
    const float4 pb = __ldg(prob4 + 2 * i + 1);

    float s0 = 0.f, s1 = 0.f, s2 = 0.f, s3 = 0.f;
    float s4 = 0.f, s5 = 0.f, s6 = 0.f, s7 = 0.f, sw = 0.f;

    // 46 strictly-positive offsets (d^2 <= 8) in 16 chunks of <=3 pairs
    switch (chunk) {
        case  0: ROWS(0,0,1,2)   ROWS(2,-2,0,0)   break; // 3 [diag]
        case  1: ROWS(0,1,-2,0)                   break; // 3
        case  2: ROWS(0,1,1,2)   ROWS(2,2,0,0)    break; // 3
        case  3: ROWS(0,2,-2,0)                   break; // 3
        case  4: ROWS(0,2,1,2)   ROWS(1,-2,-1,-1) break; // 3
        case  5: ROWS(1,-2,0,1)  ROWS(2,-1,-1,-1) break; // 3
        case  6: ROWS(1,-1,-2,0)                  break; // 3
        case  7: ROWS(1,-1,1,2)  ROWS(2,-1,0,0)   break; // 3
        case  8: ROWS(1,0,-2,0)                   break; // 3
        case  9: ROWS(1,0,1,2)   ROWS(2,-1,1,1)   break; // 3
        case 10: ROWS(1,1,-2,0)                   break; // 3
        case 11: ROWS(1,1,1,2)   ROWS(2,1,-1,-1)  break; // 3
        case 12: ROWS(1,2,-1,1)                   break; // 3
        case 13: ROWS(2,0,-2,0)                   break; // 3
        case 14: ROWS(2,0,1,2)   ROWS(2,1,0,0)    break; // 3
        case 15: ROWS(2,1,1,1)                    break; // 1
    }

    // per-thread combine (symmetry: num += P*(2s + diag*P), den += P*(sw+diag) + s)
    const float diag = (chunk == 0) ? 1.0f : 0.0f;

    float v[16];
    v[0] = pa.x * fmaf(diag, pa.x, 2.f * s0);
    v[1] = pa.y * fmaf(diag, pa.y, 2.f * s1);
    v[2] = pa.z * fmaf(diag, pa.z, 2.f * s2);
    v[3] = pa.w * fmaf(diag, pa.w, 2.f * s3);
    v[4] = pb.x * fmaf(diag, pb.x, 2.f * s4);
    v[5] = pb.y * fmaf(diag, pb.y, 2.f * s5);
    v[6] = pb.z * fmaf(diag, pb.z, 2.f * s6);
    v[7] = pb.w * fmaf(diag, pb.w, 2.f * s7);
    const float swd = sw + diag;
    v[8]  = fmaf(pa.x, swd, s0);
    v[9]  = fmaf(pa.y, swd, s1);
    v[10] = fmaf(pa.z, swd, s2);
    v[11] = fmaf(pa.w, swd, s3);
    v[12] = fmaf(pb.x, swd, s4);
    v[13] = fmaf(pb.y, swd, s5);
    v[14] = fmaf(pb.z, swd, s6);
    v[15] = fmaf(pb.w, swd, s7);

    // packed multi-value warp reduction (31 shuffles)
#pragma unroll
    for (int t = 0; t < 16; t++) v[t] += __shfl_xor_sync(FULL, v[t], 16);
    float u[8];
#pragma unroll
    for (int t = 0; t < 8; t++) {
        u[t] = (lane & 16) ? v[t + 8] : v[t];
        u[t] += __shfl_xor_sync(FULL, u[t], 8);
    }
    float w4[4];
#pragma unroll
    for (int t = 0; t < 4; t++) {
        w4[t] = (lane & 8) ? u[t + 4] : u[t];
        w4[t] += __shfl_xor_sync(FULL, w4[t], 4);
    }
    float y2[2];
#pragma unroll
    for (int t = 0; t < 2; t++) {
        y2[t] = (lane & 4) ? w4[t + 2] : w4[t];
        y2[t] += __shfl_xor_sync(FULL, y2[t], 2);
    }
    float z1 = (lane & 2) ? y2[1] : y2[0];
    z1 += __shfl_xor_sync(FULL, z1, 1);
    // lanes 2t, 2t+1 hold the warp total of v[t]

    __shared__ float sm[32 * 17];        // stride 17: conflict-free column reads
    __shared__ unsigned int s_ticket;
    if (!(lane & 1)) sm[warp * 17 + (lane >> 1)] = z1;
    __syncthreads();

    // parallel cross-warp reduce: warp c (of 16) sums component c over 32 warps
    if (tid < 512) {
        const int c  = tid >> 5;
        const int sg = tid & 31;
        float a = sm[sg * 17 + c];
#pragma unroll
        for (int o = 16; o > 0; o >>= 1) a += __shfl_xor_sync(FULL, a, o);
        if (sg == 0) g_part[c * NBLK + (int)blockIdx.x] = a;
    }

    // ---- fused finalize: last block reduces 16 x 128 partials ----
    __threadfence();
    __syncthreads();
    if (tid == 0) s_ticket = atomicAdd(&g_count, 1u);
    __syncthreads();
    if (s_ticket != NBLK - 1) return;
    __threadfence();

    if (tid < 512) {
        const int c  = tid >> 5;        // component 0..15 (one warp each)
        const int sg = tid & 31;
        const float4 p = __ldcg(reinterpret_cast<const float4*>(g_part) + c * 32 + sg);
        float a = (p.x + p.y) + (p.z + p.w);
#pragma unroll
        for (int o = 16; o > 0; o >>= 1) a += __shfl_xor_sync(FULL, a, o);
        if (sg == 0) sm[c] = a;
    }
    __syncthreads();
    if (tid == 0) {
        float loss = (float)K;
#pragma unroll
        for (int t = 0; t < 8; t++) loss -= sm[t] / sm[8 + t];
        out[0] = loss;
        g_count = 0;                    // reset for graph replay
    }
}

extern "C" void kernel_launch(void* const* d_in, const int* in_sizes, int n_in,
                              void* d_out, int out_size)
{
    const float* patch = (const float*)d_in[0];
    const float* prob  = (const float*)d_in[1];
    float* out = (float*)d_out;

    soft_ncuts_fused<<<NBLK, BLK>>>(patch, prob, out);
}

// round 14
// speedup vs baseline: 1.1747x; 1.1199x over previous
#include <cuda_runtime.h>

#define K 8
#define BLK 1024                // 32 warps: 2 rows x 16 offset chunks
#define NBLK 128                // single wave, one block per SM
#define L2E 1.4426950408889634f
#define C1  (L2E / 9.0f)

__device__ float g_part[16 * NBLK];   // transposed [component][block]
__device__ unsigned int g_count = 0;

#define FULL 0xFFFFFFFFu

// One neighbor row (DX,DY): 3 coalesced loads, then DZ pairs via shuffles only.
#define ROWS(DX, DY, DZLO, DZHI) { \
    const int xx = x + (DX); \
    const int yy = y + (DY); \
    if (xx < 8 && (unsigned)yy < 32u) {   /* warp-uniform branch */ \
        const int jr = (xx << 10) + (yy << 5) + lane; \
        const float fj = __ldg(patch + jr); \
        const float4 qa = __ldg(prob4 + 2 * jr); \
        const float4 qb = __ldg(prob4 + 2 * jr + 1); \
        _Pragma("unroll") \
        for (int dz = (DZLO); dz <= (DZHI); dz++) { \
            const int src = lane + dz; \
            const int sm5 = src & 31; \
            const float fjn = __shfl_sync(FULL, fj, sm5); \
            const float df = fi - fjn; \
            const float e2 = fmaf(df * df, -C1, \
                -(float)((DX)*(DX) + (DY)*(DY) + dz*dz) * L2E); \
            float w; asm("ex2.approx.f32 %0, %1;" : "=f"(w) : "f"(e2)); \
            w = ((unsigned)src < 32u) ? w : 0.0f; \
            s0 = fmaf(w, __shfl_sync(FULL, qa.x, sm5), s0); \
            s1 = fmaf(w, __shfl_sync(FULL, qa.y, sm5), s1); \
            s2 = fmaf(w, __shfl_sync(FULL, qa.z, sm5), s2); \
            s3 = fmaf(w, __shfl_sync(FULL, qa.w, sm5), s3); \
            s4 = fmaf(w, __shfl_sync(FULL, qb.x, sm5), s4); \
            s5 = fmaf(w, __shfl_sync(FULL, qb.y, sm5), s5); \
            s6 = fmaf(w, __shfl_sync(FULL, qb.z, sm5), s6); \
            s7 = fmaf(w, __shfl_sync(FULL, qb.w, sm5), s7); \
            sw += w; \
        } \
    } }

__global__ __launch_bounds__(BLK, 1) void soft_ncuts_fused(
    const float* __restrict__ patch,
    const float* __restrict__ prob,
    float* __restrict__ out)
{
    const int tid   = threadIdx.x;
    const int lane  = tid & 31;          // = z
    const int warp  = tid >> 5;          // 0..31
    const int chunk = warp >> 1;         // 0..15 (offset chunk)
    const int rowl  = warp & 1;          // which of the block's 2 rows
    const int gid   = (int)blockIdx.x * 2 + rowl;   // 0..255 (x,y) row id
    const int x = gid >> 5;              // 0..7
    const int y = gid & 31;              // 0..31
    const int i = (x << 10) + (y << 5) + lane;

    const float4* __restrict__ prob4 = reinterpret_cast<const float4*>(prob);
    const float fi = __ldg(patch + i);
    const float4 pa = __ldg(prob4 + 2 * i);
    const float4 pb = __ldg(prob4 + 2 * i + 1);

    float s0 = 0.f, s1 = 0.f, s2 = 0.f, s3 = 0.f;
    float s4 = 0.f, s5 = 0.f, s6 = 0.f, s7 = 0.f, sw = 0.f;

    // 46 strictly-positive offsets (d^2 <= 8) in 16 chunks of <=3 pairs
    switch (chunk) {
        case  0: ROWS(0,0,1,2)   ROWS(2,-2,0,0)   break; // 3 [diag]
        case  1: ROWS(0,1,-2,0)                   break; // 3
        case  2: ROWS(0,1,1,2)   ROWS(2,2,0,0)    break; // 3
        case  3: ROWS(0,2,-2,0)                   break; // 3
        case  4: ROWS(0,2,1,2)   ROWS(1,-2,-1,-1) break; // 3
        case  5: ROWS(1,-2,0,1)  ROWS(2,-1,-1,-1) break; // 3
        case  6: ROWS(1,-1,-2,0)                  break; // 3
        case  7: ROWS(1,-1,1,2)  ROWS(2,-1,0,0)   break; // 3
        case  8: ROWS(1,0,-2,0)                   break; // 3
        case  9: ROWS(1,0,1,2)   ROWS(2,-1,1,1)   break; // 3
        case 10: ROWS(1,1,-2,0)                   break; // 3
        case 11: ROWS(1,1,1,2)   ROWS(2,1,-1,-1)  break; // 3
        case 12: ROWS(1,2,-1,1)                   break; // 3
        case 13: ROWS(2,0,-2,0)                   break; // 3
        case 14: ROWS(2,0,1,2)   ROWS(2,1,0,0)    break; // 3
        case 15: ROWS(2,1,1,1)                    break; // 1
    }

    // per-thread combine (symmetry: num += P*(2s + diag*P), den += P*(sw+diag) + s)
    const float diag = (chunk == 0) ? 1.0f : 0.0f;

    float v[16];
    v[0] = pa.x * fmaf(diag, pa.x, 2.f * s0);
    v[1] = pa.y * fmaf(diag, pa.y, 2.f * s1);
    v[2] = pa.z * fmaf(diag, pa.z, 2.f * s2);
    v[3] = pa.w * fmaf(diag, pa.w, 2.f * s3);
    v[4] = pb.x * fmaf(diag, pb.x, 2.f * s4);
    v[5] = pb.y * fmaf(diag, pb.y, 2.f * s5);
    v[6] = pb.z * fmaf(diag, pb.z, 2.f * s6);
    v[7] = pb.w * fmaf(diag, pb.w, 2.f * s7);
    const float swd = sw + diag;
    v[8]  = fmaf(pa.x, swd, s0);
    v[9]  = fmaf(pa.y, swd, s1);
    v[10] = fmaf(pa.z, swd, s2);
    v[11] = fmaf(pa.w, swd, s3);
    v[12] = fmaf(pb.x, swd, s4);
    v[13] = fmaf(pb.y, swd, s5);
    v[14] = fmaf(pb.z, swd, s6);
    v[15] = fmaf(pb.w, swd, s7);

    // packed multi-value warp reduction (31 shuffles)
#pragma unroll
    for (int t = 0; t < 16; t++) v[t] += __shfl_xor_sync(FULL, v[t], 16);
    float u[8];
#pragma unroll
    for (int t = 0; t < 8; t++) {
        u[t] = (lane & 16) ? v[t + 8] : v[t];
        u[t] += __shfl_xor_sync(FULL, u[t], 8);
    }
    float w4[4];
#pragma unroll
    for (int t = 0; t < 4; t++) {
        w4[t] = (lane & 8) ? u[t + 4] : u[t];
        w4[t] += __shfl_xor_sync(FULL, w4[t], 4);
    }
    float y2[2];
#pragma unroll
    for (int t = 0; t < 2; t++) {
        y2[t] = (lane & 4) ? w4[t + 2] : w4[t];
        y2[t] += __shfl_xor_sync(FULL, y2[t], 2);
    }
    float z1 = (lane & 2) ? y2[1] : y2[0];
    z1 += __shfl_xor_sync(FULL, z1, 1);
    // lanes 2t, 2t+1 hold the warp total of v[t]

    __shared__ float sm[32 * 17];        // stride 17: conflict-free column reads
    __shared__ unsigned int s_ticket;
    if (!(lane & 1)) sm[warp * 17 + (lane >> 1)] = z1;
    __syncthreads();

    // parallel cross-warp reduce: warp c (of 16) sums component c over 32 warps
    if (tid < 512) {
        const int c  = tid >> 5;
        const int sg = tid & 31;
        float a = sm[sg * 17 + c];
#pragma unroll
        for (int o = 16; o > 0; o >>= 1) a += __shfl_xor_sync(FULL, a, o);
        if (sg == 0) g_part[c * NBLK + (int)blockIdx.x] = a;
    }

    // ---- fused finalize via acq_rel ticket (no explicit membars) ----
    // writers' g_part stores -> bar.sync -> tid0's release-add publishes them;
    // last block's acquire-add orders its subsequent g_part reads.
    __syncthreads();
    if (tid == 0) {
        unsigned int t;
        asm volatile("atom.add.acq_rel.gpu.global.u32 %0, [%1], %2;"
                     : "=r"(t) : "l"(&g_count), "r"(1u) : "memory");
        s_ticket = t;
    }
    __syncthreads();
    if (s_ticket != NBLK - 1) return;

    if (tid < 512) {
        const int c  = tid >> 5;        // component 0..15 (one warp each)
        const int sg = tid & 31;
        const float4 p = __ldcg(reinterpret_cast<const float4*>(g_part) + c * 32 + sg);
        float a = (p.x + p.y) + (p.z + p.w);
#pragma unroll
        for (int o = 16; o > 0; o >>= 1) a += __shfl_xor_sync(FULL, a, o);
        if (sg == 0) sm[c] = a;
    }
    __syncthreads();
    if (tid == 0) {
        float loss = (float)K;
#pragma unroll
        for (int t = 0; t < 8; t++) loss -= sm[t] / sm[8 + t];
        out[0] = loss;
        g_count = 0;                    // reset for graph replay
    }
}

extern "C" void kernel_launch(void* const* d_in, const int* in_sizes, int n_in,
                              void* d_out, int out_size)
{
    const float* patch = (const float*)d_in[0];
    const float* prob  = (const float*)d_in[1];
    float* out = (float*)d_out;

    soft_ncuts_fused<<<NBLK, BLK>>>(patch, prob, out);
}

// round 15
// speedup vs baseline: 1.1910x; 1.0139x over previous
#include <cuda_runtime.h>

#define K 8
#define BLK 1024                // 32 warps: 2 rows x 16 offset chunks
#define NBLK 128                // single wave, one block per SM
#define L2E 1.4426950408889634f
#define C1  (L2E / 9.0f)

__device__ float g_part[16 * NBLK];   // transposed [component][block]
__device__ unsigned int g_count = 0;

#define FULL 0xFFFFFFFFu

// One neighbor row (DX,DY): 3 coalesced loads, then DZ pairs via shuffles only.
#define ROWS(DX, DY, DZLO, DZHI) { \
    const int xx = x + (DX); \
    const int yy = y + (DY); \
    if (xx < 8 && (unsigned)yy < 32u) {   /* warp-uniform branch */ \
        const int jr = (xx << 10) + (yy << 5) + lane; \
        const float fj = __ldg(patch + jr); \
        const float4 qa = __ldg(prob4 + 2 * jr); \
        const float4 qb = __ldg(prob4 + 2 * jr + 1); \
        _Pragma("unroll") \
        for (int dz = (DZLO); dz <= (DZHI); dz++) { \
            const int src = lane + dz; \
            const int sm5 = src & 31; \
            const float fjn = __shfl_sync(FULL, fj, sm5); \
            const float df = fi - fjn; \
            const float e2 = fmaf(df * df, -C1, \
                -(float)((DX)*(DX) + (DY)*(DY) + dz*dz) * L2E); \
            float w; asm("ex2.approx.f32 %0, %1;" : "=f"(w) : "f"(e2)); \
            w = ((unsigned)src < 32u) ? w : 0.0f; \
            s0 = fmaf(w, __shfl_sync(FULL, qa.x, sm5), s0); \
            s1 = fmaf(w, __shfl_sync(FULL, qa.y, sm5), s1); \
            s2 = fmaf(w, __shfl_sync(FULL, qa.z, sm5), s2); \
            s3 = fmaf(w, __shfl_sync(FULL, qa.w, sm5), s3); \
            s4 = fmaf(w, __shfl_sync(FULL, qb.x, sm5), s4); \
            s5 = fmaf(w, __shfl_sync(FULL, qb.y, sm5), s5); \
            s6 = fmaf(w, __shfl_sync(FULL, qb.z, sm5), s6); \
            s7 = fmaf(w, __shfl_sync(FULL, qb.w, sm5), s7); \
            sw += w; \
        } \
    } }

__global__ __launch_bounds__(BLK, 1) void soft_ncuts_fused(
    const float* __restrict__ patch,
    const float* __restrict__ prob,
    float* __restrict__ out)
{
    const int tid   = threadIdx.x;
    const int lane  = tid & 31;          // = z
    const int warp  = tid >> 5;          // 0..31
    const int chunk = warp >> 1;         // 0..15 (offset chunk)
    const int rowl  = warp & 1;          // which of the block's 2 rows
    const int gid   = (int)blockIdx.x * 2 + rowl;   // 0..255 (x,y) row id
    const int x = gid >> 5;              // 0..7
    const int y = gid & 31;              // 0..31
    const int i = (x << 10) + (y << 5) + lane;

    const float4* __restrict__ prob4 = reinterpret_cast<const float4*>(prob);
    const float fi = __ldg(patch + i);
    const float4 pa = __ldg(prob4 + 2 * i);
    const float4 pb = __ldg(prob4 + 2 * i + 1);

    float s0 = 0.f, s1 = 0.f, s2 = 0.f, s3 = 0.f;
    float s4 = 0.f, s5 = 0.f, s6 = 0.f, s7 = 0.f, sw = 0.f;

    // 46 strictly-positive offsets (d^2 <= 8) in 16 chunks of <=3 pairs
    switch (chunk) {
        case  0: ROWS(0,0,1,2)   ROWS(2,-2,0,0)   break; // 3 [diag]
        case  1: ROWS(0,1,-2,0)                   break; // 3
        case  2: ROWS(0,1,1,2)   ROWS(2,2,0,0)    break; // 3
        case  3: ROWS(0,2,-2,0)                   break; // 3
        case  4: ROWS(0,2,1,2)   ROWS(1,-2,-1,-1) break; // 3
        case  5: ROWS(1,-2,0,1)  ROWS(2,-1,-1,-1) break; // 3
        case  6: ROWS(1,-1,-2,0)                  break; // 3
        case  7: ROWS(1,-1,1,2)  ROWS(2,-1,0,0)   break; // 3
        case  8: ROWS(1,0,-2,0)                   break; // 3
        case  9: ROWS(1,0,1,2)   ROWS(2,-1,1,1)   break; // 3
        case 10: ROWS(1,1,-2,0)                   break; // 3
        case 11: ROWS(1,1,1,2)   ROWS(2,1,-1,-1)  break; // 3
        case 12: ROWS(1,2,-1,1)                   break; // 3
        case 13: ROWS(2,0,-2,0)                   break; // 3
        case 14: ROWS(2,0,1,2)   ROWS(2,1,0,0)    break; // 3
        case 15: ROWS(2,1,1,1)                    break; // 1
    }

    // per-thread combine (symmetry: num += P*(2s + diag*P), den += P*(sw+diag) + s)
    const float diag = (chunk == 0) ? 1.0f : 0.0f;

    float v[16];
    v[0] = pa.x * fmaf(diag, pa.x, 2.f * s0);
    v[1] = pa.y * fmaf(diag, pa.y, 2.f * s1);
    v[2] = pa.z * fmaf(diag, pa.z, 2.f * s2);
    v[3] = pa.w * fmaf(diag, pa.w, 2.f * s3);
    v[4] = pb.x * fmaf(diag, pb.x, 2.f * s4);
    v[5] = pb.y * fmaf(diag, pb.y, 2.f * s5);
    v[6] = pb.z * fmaf(diag, pb.z, 2.f * s6);
    v[7] = pb.w * fmaf(diag, pb.w, 2.f * s7);
    const float swd = sw + diag;
    v[8]  = fmaf(pa.x, swd, s0);
    v[9]  = fmaf(pa.y, swd, s1);
    v[10] = fmaf(pa.z, swd, s2);
    v[11] = fmaf(pa.w, swd, s3);
    v[12] = fmaf(pb.x, swd, s4);
    v[13] = fmaf(pb.y, swd, s5);
    v[14] = fmaf(pb.z, swd, s6);
    v[15] = fmaf(pb.w, swd, s7);

    // packed multi-value warp reduction (31 shuffles)
#pragma unroll
    for (int t = 0; t < 16; t++) v[t] += __shfl_xor_sync(FULL, v[t], 16);
    float u[8];
#pragma unroll
    for (int t = 0; t < 8; t++) {
        u[t] = (lane & 16) ? v[t + 8] : v[t];
        u[t] += __shfl_xor_sync(FULL, u[t], 8);
    }
    float w4[4];
#pragma unroll
    for (int t = 0; t < 4; t++) {
        w4[t] = (lane & 8) ? u[t + 4] : u[t];
        w4[t] += __shfl_xor_sync(FULL, w4[t], 4);
    }
    float y2[2];
#pragma unroll
    for (int t = 0; t < 2; t++) {
        y2[t] = (lane & 4) ? w4[t + 2] : w4[t];
        y2[t] += __shfl_xor_sync(FULL, y2[t], 2);
    }
    float z1 = (lane & 2) ? y2[1] : y2[0];
    z1 += __shfl_xor_sync(FULL, z1, 1);
    // lanes 2t, 2t+1 hold the warp total of v[t]

    __shared__ float sm[32 * 17];        // stride 17: conflict-free column reads
    __shared__ unsigned int s_ticket;
    if (!(lane & 1)) sm[warp * 17 + (lane >> 1)] = z1;
    __syncthreads();

    // parallel cross-warp reduce: warp c (of 16) sums component c over 32 warps
    if (tid < 512) {
        const int c  = tid >> 5;
        const int sg = tid & 31;
        float a = sm[sg * 17 + c];
#pragma unroll
        for (int o = 16; o > 0; o >>= 1) a += __shfl_xor_sync(FULL, a, o);
        if (sg == 0) g_part[c * NBLK + (int)blockIdx.x] = a;
    }

    // ---- fused finalize via acq_rel ticket (no explicit membars) ----
    __syncthreads();
    if (tid == 0) {
        unsigned int t;
        asm volatile("atom.add.acq_rel.gpu.global.u32 %0, [%1], %2;"
                     : "=r"(t) : "l"(&g_count), "r"(1u) : "memory");
        s_ticket = t;
    }
    __syncthreads();
    if (s_ticket != NBLK - 1) return;

    if (tid < 512) {
        const int c  = tid >> 5;        // component 0..15 (one warp each)
        const int sg = tid & 31;
        const float4 p = __ldcg(reinterpret_cast<const float4*>(g_part) + c * 32 + sg);
        float a = (p.x + p.y) + (p.z + p.w);
#pragma unroll
        for (int o = 16; o > 0; o >>= 1) a += __shfl_xor_sync(FULL, a, o);
        if (sg == 0) sm[c] = a;
    }
    __syncthreads();
    // parallel epilogue: lane t of warp 0 computes num_t/den_t (approx div),
    // 3-step shuffle sum over lanes 0-7, lane 0 writes the loss.
    if (tid < 8) {
        float r = __fdividef(sm[tid], sm[8 + tid]);
        r += __shfl_xor_sync(0xFFu, r, 1);
        r += __shfl_xor_sync(0xFFu, r, 2);
        r += __shfl_xor_sync(0xFFu, r, 4);
        if (tid == 0) {
            out[0] = (float)K - r;
            g_count = 0;                 // reset for graph replay
        }
    }
}

extern "C" void kernel_launch(void* const* d_in, const int* in_sizes, int n_in,
                              void* d_out, int out_size)
{
    const float* patch = (const float*)d_in[0];
    const float* prob  = (const float*)d_in[1];
    float* out = (float*)d_out;

    soft_ncuts_fused<<<NBLK, BLK>>>(patch, prob, out);
}

// round 16
// speedup vs baseline: 1.2250x; 1.0286x over previous
#include <cuda_runtime.h>

#define K 8
#define BLK 1024                // 32 warps: 2 rows x 16 offset chunks
#define NBLK 128                // single wave, one block per SM
#define L2E 1.4426950408889634f
#define C1  (L2E / 9.0f)

__device__ float g_part[16 * NBLK];   // transposed [component][block]
__device__ unsigned int g_count = 0;

#define FULL 0xFFFFFFFFu
#define BAR512() asm volatile("bar.sync 1, 512;" ::: "memory")

// One neighbor row (DX,DY): 3 coalesced loads, then DZ pairs via shuffles only.
#define ROWS(DX, DY, DZLO, DZHI) { \
    const int xx = x + (DX); \
    const int yy = y + (DY); \
    if (xx < 8 && (unsigned)yy < 32u) {   /* warp-uniform branch */ \
        const int jr = (xx << 10) + (yy << 5) + lane; \
        const float fj = __ldg(patch + jr); \
        const float4 qa = __ldg(prob4 + 2 * jr); \
        const float4 qb = __ldg(prob4 + 2 * jr + 1); \
        _Pragma("unroll") \
        for (int dz = (DZLO); dz <= (DZHI); dz++) { \
            const int src = lane + dz; \
            const int sm5 = src & 31; \
            const float fjn = __shfl_sync(FULL, fj, sm5); \
            const float df = fi - fjn; \
            const float e2 = fmaf(df * df, -C1, \
                -(float)((DX)*(DX) + (DY)*(DY) + dz*dz) * L2E); \
            float w; asm("ex2.approx.f32 %0, %1;" : "=f"(w) : "f"(e2)); \
            w = ((unsigned)src < 32u) ? w : 0.0f; \
            s0 = fmaf(w, __shfl_sync(FULL, qa.x, sm5), s0); \
            s1 = fmaf(w, __shfl_sync(FULL, qa.y, sm5), s1); \
            s2 = fmaf(w, __shfl_sync(FULL, qa.z, sm5), s2); \
            s3 = fmaf(w, __shfl_sync(FULL, qa.w, sm5), s3); \
            s4 = fmaf(w, __shfl_sync(FULL, qb.x, sm5), s4); \
            s5 = fmaf(w, __shfl_sync(FULL, qb.y, sm5), s5); \
            s6 = fmaf(w, __shfl_sync(FULL, qb.z, sm5), s6); \
            s7 = fmaf(w, __shfl_sync(FULL, qb.w, sm5), s7); \
            sw += w; \
        } \
    } }

__global__ __launch_bounds__(BLK, 1) void soft_ncuts_fused(
    const float* __restrict__ patch,
    const float* __restrict__ prob,
    float* __restrict__ out)
{
    const int tid   = threadIdx.x;
    const int lane  = tid & 31;          // = z
    const int warp  = tid >> 5;          // 0..31
    const int chunk = warp >> 1;         // 0..15 (offset chunk)
    const int rowl  = warp & 1;          // which of the block's 2 rows
    const int gid   = (int)blockIdx.x * 2 + rowl;   // 0..255 (x,y) row id
    const int x = gid >> 5;              // 0..7
    const int y = gid & 31;              // 0..31
    const int i = (x << 10) + (y << 5) + lane;

    const float4* __restrict__ prob4 = reinterpret_cast<const float4*>(prob);
    const float fi = __ldg(patch + i);
    const float4 pa = __ldg(prob4 + 2 * i);
    const float4 pb = __ldg(prob4 + 2 * i + 1);

    float s0 = 0.f, s1 = 0.f, s2 = 0.f, s3 = 0.f;
    float s4 = 0.f, s5 = 0.f, s6 = 0.f, s7 = 0.f, sw = 0.f;

    // 46 strictly-positive offsets (d^2 <= 8) in 16 chunks of <=3 pairs
    switch (chunk) {
        case  0: ROWS(0,0,1,2)   ROWS(2,-2,0,0)   break; // 3 [diag]
        case  1: ROWS(0,1,-2,0)                   break; // 3
        case  2: ROWS(0,1,1,2)   ROWS(2,2,0,0)    break; // 3
        case  3: ROWS(0,2,-2,0)                   break; // 3
        case  4: ROWS(0,2,1,2)   ROWS(1,-2,-1,-1) break; // 3
        case  5: ROWS(1,-2,0,1)  ROWS(2,-1,-1,-1) break; // 3
        case  6: ROWS(1,-1,-2,0)                  break; // 3
        case  7: ROWS(1,-1,1,2)  ROWS(2,-1,0,0)   break; // 3
        case  8: ROWS(1,0,-2,0)                   break; // 3
        case  9: ROWS(1,0,1,2)   ROWS(2,-1,1,1)   break; // 3
        case 10: ROWS(1,1,-2,0)                   break; // 3
        case 11: ROWS(1,1,1,2)   ROWS(2,1,-1,-1)  break; // 3
        case 12: ROWS(1,2,-1,1)                   break; // 3
        case 13: ROWS(2,0,-2,0)                   break; // 3
        case 14: ROWS(2,0,1,2)   ROWS(2,1,0,0)    break; // 3
        case 15: ROWS(2,1,1,1)                    break; // 1
    }

    // per-thread combine (symmetry: num += P*(2s + diag*P), den += P*(sw+diag) + s)
    const float diag = (chunk == 0) ? 1.0f : 0.0f;

    float v[16];
    v[0] = pa.x * fmaf(diag, pa.x, 2.f * s0);
    v[1] = pa.y * fmaf(diag, pa.y, 2.f * s1);
    v[2] = pa.z * fmaf(diag, pa.z, 2.f * s2);
    v[3] = pa.w * fmaf(diag, pa.w, 2.f * s3);
    v[4] = pb.x * fmaf(diag, pb.x, 2.f * s4);
    v[5] = pb.y * fmaf(diag, pb.y, 2.f * s5);
    v[6] = pb.z * fmaf(diag, pb.z, 2.f * s6);
    v[7] = pb.w * fmaf(diag, pb.w, 2.f * s7);
    const float swd = sw + diag;
    v[8]  = fmaf(pa.x, swd, s0);
    v[9]  = fmaf(pa.y, swd, s1);
    v[10] = fmaf(pa.z, swd, s2);
    v[11] = fmaf(pa.w, swd, s3);
    v[12] = fmaf(pb.x, swd, s4);
    v[13] = fmaf(pb.y, swd, s5);
    v[14] = fmaf(pb.z, swd, s6);
    v[15] = fmaf(pb.w, swd, s7);

    // packed multi-value warp reduction (31 shuffles)
#pragma unroll
    for (int t = 0; t < 16; t++) v[t] += __shfl_xor_sync(FULL, v[t], 16);
    float u[8];
#pragma unroll
    for (int t = 0; t < 8; t++) {
        u[t] = (lane & 16) ? v[t + 8] : v[t];
        u[t] += __shfl_xor_sync(FULL, u[t], 8);
    }
    float w4[4];
#pragma unroll
    for (int t = 0; t < 4; t++) {
        w4[t] = (lane & 8) ? u[t + 4] : u[t];
        w4[t] += __shfl_xor_sync(FULL, w4[t], 4);
    }
    float y2[2];
#pragma unroll
    for (int t = 0; t < 2; t++) {
        y2[t] = (lane & 4) ? w4[t + 2] : w4[t];
        y2[t] += __shfl_xor_sync(FULL, y2[t], 2);
    }
    float z1 = (lane & 2) ? y2[1] : y2[0];
    z1 += __shfl_xor_sync(FULL, z1, 1);
    // lanes 2t, 2t+1 hold the warp total of v[t]

    __shared__ float sm[32 * 17];        // stride 17: conflict-free column reads
    __shared__ unsigned int s_ticket;
    if (!(lane & 1)) sm[warp * 17 + (lane >> 1)] = z1;
    __syncthreads();                     // full block: publish sm[] to warps 0-15

    // warps 16-31 are done: retire them, tail runs with 512 threads
    if (warp >= 16) return;

    // parallel cross-warp reduce: warp c (of 16) sums component c over 32 warps
    {
        const int c  = warp;
        const int sg = lane;
        float a = sm[sg * 17 + c];
#pragma unroll
        for (int o = 16; o > 0; o >>= 1) a += __shfl_xor_sync(FULL, a, o);
        if (sg == 0) g_part[c * NBLK + (int)blockIdx.x] = a;
    }

    // ---- fused finalize via acq_rel ticket (no explicit membars) ----
    BAR512();                            // g_part stores done block-wide
    if (tid == 0) {
        unsigned int t;
        asm volatile("atom.add.acq_rel.gpu.global.u32 %0, [%1], %2;"
                     : "=r"(t) : "l"(&g_count), "r"(1u) : "memory");
        s_ticket = t;
    }
    BAR512();                            // publish s_ticket
    if (s_ticket != NBLK - 1) return;

    {
        const int c  = warp;             // component 0..15 (one warp each)
        const int sg = lane;
        const float4 p = __ldcg(reinterpret_cast<const float4*>(g_part) + c * 32 + sg);
        float a = (p.x + p.y) + (p.z + p.w);
#pragma unroll
        for (int o = 16; o > 0; o >>= 1) a += __shfl_xor_sync(FULL, a, o);
        if (sg == 0) sm[c] = a;
    }
    BAR512();
    // parallel epilogue: lane t computes num_t/den_t (approx div),
    // 3-step shuffle sum over lanes 0-7, lane 0 writes the loss.
    if (tid < 8) {
        float r = __fdividef(sm[tid], sm[8 + tid]);
        r += __shfl_xor_sync(0xFFu, r, 1);
        r += __shfl_xor_sync(0xFFu, r, 2);
        r += __shfl_xor_sync(0xFFu, r, 4);
        if (tid == 0) {
            out[0] = (float)K - r;
            g_count = 0;                 // reset for graph replay
        }
    }
}

extern "C" void kernel_launch(void* const* d_in, const int* in_sizes, int n_in,
                              void* d_out, int out_size)
{
    const float* patch = (const float*)d_in[0];
    const float* prob  = (const float*)d_in[1];
    float* out = (float*)d_out;

    soft_ncuts_fused<<<NBLK, BLK>>>(patch, prob, out);
}

// round 17
// speedup vs baseline: 1.3142x; 1.0728x over previous
#include <cuda_runtime.h>

#define K 8
#define BLK 1024                // 32 warps: 2 rows x 16 offset chunks
#define NBLK 128                // single wave, one block per SM
#define L2E 1.4426950408889634f
#define C1  (L2E / 9.0f)

__device__ float g_part[16 * NBLK];   // transposed [component][block]
__device__ unsigned int g_count = 0;

#define FULL 0xFFFFFFFFu
#define BAR512() asm volatile("bar.sync 1, 512;" ::: "memory")

// One neighbor row (DX,DY): 3 coalesced loads, then DZ pairs via shuffles only.
#define ROWS(DX, DY, DZLO, DZHI) { \
    const int xx = x + (DX); \
    const int yy = y + (DY); \
    if (xx < 8 && (unsigned)yy < 32u) {   /* warp-uniform branch */ \
        const int jr = (xx << 10) + (yy << 5) + lane; \
        const float fj = __ldg(patch + jr); \
        const float4 qa = __ldg(prob4 + 2 * jr); \
        const float4 qb = __ldg(prob4 + 2 * jr + 1); \
        _Pragma("unroll") \
        for (int dz = (DZLO); dz <= (DZHI); dz++) { \
            const int src = lane + dz; \
            const int sm5 = src & 31; \
            const float fjn = __shfl_sync(FULL, fj, sm5); \
            const float df = fi - fjn; \
            const float e2 = fmaf(df * df, -C1, \
                -(float)((DX)*(DX) + (DY)*(DY) + dz*dz) * L2E); \
            float w; asm("ex2.approx.f32 %0, %1;" : "=f"(w) : "f"(e2)); \
            w = ((unsigned)src < 32u) ? w : 0.0f; \
            s0 = fmaf(w, __shfl_sync(FULL, qa.x, sm5), s0); \
            s1 = fmaf(w, __shfl_sync(FULL, qa.y, sm5), s1); \
            s2 = fmaf(w, __shfl_sync(FULL, qa.z, sm5), s2); \
            s3 = fmaf(w, __shfl_sync(FULL, qa.w, sm5), s3); \
            s4 = fmaf(w, __shfl_sync(FULL, qb.x, sm5), s4); \
            s5 = fmaf(w, __shfl_sync(FULL, qb.y, sm5), s5); \
            s6 = fmaf(w, __shfl_sync(FULL, qb.z, sm5), s6); \
            s7 = fmaf(w, __shfl_sync(FULL, qb.w, sm5), s7); \
            sw += w; \
        } \
    } }

__global__ __launch_bounds__(BLK, 1) void soft_ncuts_fused(
    const float* __restrict__ patch,
    const float* __restrict__ prob,
    float* __restrict__ out)
{
    const int tid   = threadIdx.x;
    const int lane  = tid & 31;          // = z
    const int warp  = tid >> 5;          // 0..31
    const int chunk = warp >> 1;         // 0..15 (offset chunk)
    const int rowl  = warp & 1;          // which of the block's 2 rows
    const int gid   = (int)blockIdx.x * 2 + rowl;   // 0..255 (x,y) row id
    const int x = gid >> 5;              // 0..7
    const int y = gid & 31;              // 0..31
    const int i = (x << 10) + (y << 5) + lane;

    const float4* __restrict__ prob4 = reinterpret_cast<const float4*>(prob);
    const float fi = __ldg(patch + i);
    const float4 pa = __ldg(prob4 + 2 * i);
    const float4 pb = __ldg(prob4 + 2 * i + 1);

    float s0 = 0.f, s1 = 0.f, s2 = 0.f, s3 = 0.f;
    float s4 = 0.f, s5 = 0.f, s6 = 0.f, s7 = 0.f, sw = 0.f;

    // 46 strictly-positive offsets (d^2 <= 8) in 16 chunks of <=3 pairs
    switch (chunk) {
        case  0: ROWS(0,0,1,2)   ROWS(2,-2,0,0)   break; // 3 [diag]
        case  1: ROWS(0,1,-2,0)                   break; // 3
        case  2: ROWS(0,1,1,2)   ROWS(2,2,0,0)    break; // 3
        case  3: ROWS(0,2,-2,0)                   break; // 3
        case  4: ROWS(0,2,1,2)   ROWS(1,-2,-1,-1) break; // 3
        case  5: ROWS(1,-2,0,1)  ROWS(2,-1,-1,-1) break; // 3
        case  6: ROWS(1,-1,-2,0)                  break; // 3
        case  7: ROWS(1,-1,1,2)  ROWS(2,-1,0,0)   break; // 3
        case  8: ROWS(1,0,-2,0)                   break; // 3
        case  9: ROWS(1,0,1,2)   ROWS(2,-1,1,1)   break; // 3
        case 10: ROWS(1,1,-2,0)                   break; // 3
        case 11: ROWS(1,1,1,2)   ROWS(2,1,-1,-1)  break; // 3
        case 12: ROWS(1,2,-1,1)                   break; // 3
        case 13: ROWS(2,0,-2,0)                   break; // 3
        case 14: ROWS(2,0,1,2)   ROWS(2,1,0,0)    break; // 3
        case 15: ROWS(2,1,1,1)                    break; // 1
    }

    // per-thread combine (symmetry: num += P*(2s + diag*P), den += P*(sw+diag) + s)
    const float diag = (chunk == 0) ? 1.0f : 0.0f;

    float v[16];
    v[0] = pa.x * fmaf(diag, pa.x, 2.f * s0);
    v[1] = pa.y * fmaf(diag, pa.y, 2.f * s1);
    v[2] = pa.z * fmaf(diag, pa.z, 2.f * s2);
    v[3] = pa.w * fmaf(diag, pa.w, 2.f * s3);
    v[4] = pb.x * fmaf(diag, pb.x, 2.f * s4);
    v[5] = pb.y * fmaf(diag, pb.y, 2.f * s5);
    v[6] = pb.z * fmaf(diag, pb.z, 2.f * s6);
    v[7] = pb.w * fmaf(diag, pb.w, 2.f * s7);
    const float swd = sw + diag;
    v[8]  = fmaf(pa.x, swd, s0);
    v[9]  = fmaf(pa.y, swd, s1);
    v[10] = fmaf(pa.z, swd, s2);
    v[11] = fmaf(pa.w, swd, s3);
    v[12] = fmaf(pb.x, swd, s4);
    v[13] = fmaf(pb.y, swd, s5);
    v[14] = fmaf(pb.z, swd, s6);
    v[15] = fmaf(pb.w, swd, s7);

    // packed multi-value warp reduction (31 shuffles)
#pragma unroll
    for (int t = 0; t < 16; t++) v[t] += __shfl_xor_sync(FULL, v[t], 16);
    float u[8];
#pragma unroll
    for (int t = 0; t < 8; t++) {
        u[t] = (lane & 16) ? v[t + 8] : v[t];
        u[t] += __shfl_xor_sync(FULL, u[t], 8);
    }
    float w4[4];
#pragma unroll
    for (int t = 0; t < 4; t++) {
        w4[t] = (lane & 8) ? u[t + 4] : u[t];
        w4[t] += __shfl_xor_sync(FULL, w4[t], 4);
    }
    float y2[2];
#pragma unroll
    for (int t = 0; t < 2; t++) {
        y2[t] = (lane & 4) ? w4[t + 2] : w4[t];
        y2[t] += __shfl_xor_sync(FULL, y2[t], 2);
    }
    float z1 = (lane & 2) ? y2[1] : y2[0];
    z1 += __shfl_xor_sync(FULL, z1, 1);
    // lanes 2t, 2t+1 hold the warp total of v[t]

    __shared__ float sm[32 * 17];        // stride 17: conflict-free column reads
    __shared__ unsigned int s_ticket;
    if (!(lane & 1)) sm[warp * 17 + (lane >> 1)] = z1;
    __syncthreads();                     // full block: publish sm[] to warps 0-15

    // warps 16-31 are done: retire them, tail runs with 512 threads
    if (warp >= 16) return;

    // parallel cross-warp reduce: warp c (of 16) sums component c over 32 warps
    {
        const int c  = warp;
        const int sg = lane;
        float a = sm[sg * 17 + c];
#pragma unroll
        for (int o = 16; o > 0; o >>= 1) a += __shfl_xor_sync(FULL, a, o);
        if (sg == 0) g_part[c * NBLK + (int)blockIdx.x] = a;
    }

    // ---- fused finalize via acq_rel ticket (no explicit membars) ----
    BAR512();                            // g_part stores done block-wide
    if (tid == 0) {
        unsigned int t;
        asm volatile("atom.add.acq_rel.gpu.global.u32 %0, [%1], %2;"
                     : "=r"(t) : "l"(&g_count), "r"(1u) : "memory");
        s_ticket = t;
    }
    BAR512();                            // publish s_ticket
    if (s_ticket != NBLK - 1) return;

    {
        const int c  = warp;             // component 0..15 (one warp each)
        const int sg = lane;
        const float4 p = __ldcg(reinterpret_cast<const float4*>(g_part) + c * 32 + sg);
        float a = (p.x + p.y) + (p.z + p.w);
#pragma unroll
        for (int o = 16; o > 0; o >>= 1) a += __shfl_xor_sync(FULL, a, o);
        if (sg == 0) sm[c] = a;
    }
    BAR512();
    // parallel epilogue: lane t computes num_t/den_t (approx div),
    // 3-step shuffle sum over lanes 0-7, lane 0 writes the loss.
    if (tid < 8) {
        float r = __fdividef(sm[tid], sm[8 + tid]);
        r += __shfl_xor_sync(0xFFu, r, 1);
        r += __shfl_xor_sync(0xFFu, r, 2);
        r += __shfl_xor_sync(0xFFu, r, 4);
        if (tid == 0) {
            out[0] = (float)K - r;
            g_count = 0;                 // reset for graph replay
        }
    }
}

extern "C" void kernel_launch(void* const* d_in, const int* in_sizes, int n_in,
                              void* d_out, int out_size)
{
    const float* patch = (const float*)d_in[0];
    const float* prob  = (const float*)d_in[1];
    float* out = (float*)d_out;

    soft_ncuts_fused<<<NBLK, BLK>>>(patch, prob, out);
}